// round 3
// baseline (speedup 1.0000x reference)
#include <cuda_runtime.h>

#define NN 100000
#define NE 1600000
#define NGR 512
#define FIN 7
#define HID 128

// ---------------- scratch (static device globals) ----------------
__device__ __align__(16) float d_hw[(size_t)NN * HID];
__device__ __align__(16) float d_h [(size_t)NN * HID];
__device__ float d_dinv[NN];
__device__ int   d_counts[NN];
__device__ int   d_cursor[NN];
__device__ int   d_off[NN + 1];
__device__ int   d_csrc[NE];
__device__ float d_cnorm[NE];
__device__ float d_pool[NGR * HID];
__device__ float d_cnt[NGR];
__device__ int   d_is64_ei;
__device__ int   d_is64_batch;

// flag-dispatched index load (int64 vs int32 buffers)
__device__ __forceinline__ int load_idx(const void* p, int is64, long long i) {
    return is64 ? (int)((const long long*)p)[i] : ((const int*)p)[i];
}

// ---------------- dtype probe ----------------
// int64 little-endian values < 2^31 have all odd 32-bit words == 0.
// Probe first 2048 words (8 KB) — in-bounds for either dtype.
__global__ void k_detect(const void* ei, const void* batch) {
    const int* w1 = (const int*)ei;
    const int* w2 = (const int*)batch;
    int nz1 = 0, nz2 = 0;
    for (int i = 1; i < 2048; i += 2) { nz1 |= w1[i]; nz2 |= w2[i]; }
    d_is64_ei    = (nz1 == 0);
    d_is64_batch = (nz2 == 0);
}

// ---------------- init ----------------
__global__ void k_zero() {
    int i = blockIdx.x * blockDim.x + threadIdx.x;
    int stride = gridDim.x * blockDim.x;
    for (int t = i; t < NN; t += stride) { d_counts[t] = 0; d_cursor[t] = 0; }
    for (int t = i; t < NGR * HID; t += stride) d_pool[t] = 0.f;
    for (int t = i; t < NGR; t += stride) d_cnt[t] = 0.f;
}

// ---------------- degree histogram over edge destinations ----------------
__global__ void k_hist(const void* __restrict__ ei) {
    int e = blockIdx.x * blockDim.x + threadIdx.x;
    if (e >= NE) return;
    unsigned d = (unsigned)load_idx(ei, d_is64_ei, (long long)NE + e);
    if (d < NN) atomicAdd(&d_counts[d], 1);
}

__global__ void k_dinv() {
    int i = blockIdx.x * blockDim.x + threadIdx.x;
    if (i < NN) d_dinv[i] = rsqrtf((float)d_counts[i] + 1.0f);  // +1 self-loop
}

// ---------------- single-block exclusive scan ----------------
__global__ void k_scan() {
    __shared__ int s[1024];
    int t = threadIdx.x;
    const int CH = (NN + 1023) / 1024;
    int lo = t * CH;
    int hi = lo + CH; if (hi > NN) hi = NN; if (lo > NN) lo = NN;
    int sum = 0;
    for (int i = lo; i < hi; i++) sum += d_counts[i];
    s[t] = sum;
    __syncthreads();
    for (int ofs = 1; ofs < 1024; ofs <<= 1) {
        int v = 0;
        if (t >= ofs) v = s[t - ofs];
        __syncthreads();
        if (t >= ofs) s[t] += v;
        __syncthreads();
    }
    int run = (t == 0) ? 0 : s[t - 1];
    for (int i = lo; i < hi; i++) { d_off[i] = run; run += d_counts[i]; }
    if (t == 1023) d_off[NN] = s[1023];
}

// ---------------- scatter edges into CSR (by dst) ----------------
__global__ void k_scatter(const void* __restrict__ ei) {
    int e = blockIdx.x * blockDim.x + threadIdx.x;
    if (e >= NE) return;
    int is64 = d_is64_ei;
    unsigned s = (unsigned)load_idx(ei, is64, e);
    unsigned d = (unsigned)load_idx(ei, is64, (long long)NE + e);
    if (s >= NN || d >= NN) return;
    int pos = d_off[d] + atomicAdd(&d_cursor[d], 1);
    d_csrc[pos] = (int)s;
    d_cnorm[pos] = d_dinv[s] * d_dinv[d];
}

// ---------------- layer 1 GEMM: x[N,7] @ W1[7,128] -> d_hw ----------------
__global__ void k_gemm7(const float* __restrict__ x, const float* __restrict__ W1) {
    int idx = blockIdx.x * blockDim.x + threadIdx.x;
    if (idx >= NN * HID) return;
    int n = idx >> 7, j = idx & 127;
    float acc = 0.f;
#pragma unroll
    for (int k = 0; k < FIN; k++)
        acc += __ldg(&x[n * FIN + k]) * __ldg(&W1[k * HID + j]);
    d_hw[idx] = acc;
}

// ---------------- 128x128 GEMM: relu(d_h) @ W -> d_hw ----------------
__global__ void __launch_bounds__(256) k_gemm128(const float* __restrict__ W) {
    __shared__ __align__(16) float hs[32 * 128];
    __shared__ __align__(16) float ws[32 * 128];
    const int tid = threadIdx.x;
    const int node0 = blockIdx.x * 32;

    {
        const float4* hin4 = (const float4*)(d_h + (size_t)node0 * HID);
        float4* hs4 = (float4*)hs;
#pragma unroll
        for (int i = 0; i < 4; i++) {
            float4 v = hin4[tid + i * 256];
            v.x = fmaxf(v.x, 0.f); v.y = fmaxf(v.y, 0.f);
            v.z = fmaxf(v.z, 0.f); v.w = fmaxf(v.w, 0.f);
            hs4[tid + i * 256] = v;
        }
    }

    const int tn = tid & 31;
    const int tm = tid >> 5;
    const int c0 = tn * 4;
    const int r0 = tm * 4;
    float acc[4][4] = {};

    for (int kc = 0; kc < 4; kc++) {
        __syncthreads();
        {
            const float4* W4 = (const float4*)(W + kc * 32 * HID);
            float4* ws4 = (float4*)ws;
#pragma unroll
            for (int i = 0; i < 4; i++) ws4[tid + i * 256] = W4[tid + i * 256];
        }
        __syncthreads();
#pragma unroll
        for (int kk = 0; kk < 32; kk++) {
            const int k = kc * 32 + kk;
            float4 b = *(const float4*)&ws[kk * 128 + c0];
            float a0 = hs[(r0 + 0) * 128 + k];
            float a1 = hs[(r0 + 1) * 128 + k];
            float a2 = hs[(r0 + 2) * 128 + k];
            float a3 = hs[(r0 + 3) * 128 + k];
            acc[0][0] += a0 * b.x; acc[0][1] += a0 * b.y; acc[0][2] += a0 * b.z; acc[0][3] += a0 * b.w;
            acc[1][0] += a1 * b.x; acc[1][1] += a1 * b.y; acc[1][2] += a1 * b.z; acc[1][3] += a1 * b.w;
            acc[2][0] += a2 * b.x; acc[2][1] += a2 * b.y; acc[2][2] += a2 * b.z; acc[2][3] += a2 * b.w;
            acc[3][0] += a3 * b.x; acc[3][1] += a3 * b.y; acc[3][2] += a3 * b.z; acc[3][3] += a3 * b.w;
        }
    }

#pragma unroll
    for (int u = 0; u < 4; u++) {
        float4 o = make_float4(acc[u][0], acc[u][1], acc[u][2], acc[u][3]);
        *(float4*)&d_hw[(size_t)(node0 + r0 + u) * HID + c0] = o;
    }
}

// ---------------- normalized aggregation: d_h = norm-agg(d_hw) + b --------------
__global__ void __launch_bounds__(128) k_agg(const float* __restrict__ b) {
    const int i = blockIdx.x;
    const int j = threadIdx.x;
    const float di = d_dinv[i];
    float acc = di * di * d_hw[(size_t)i * HID + j];   // self-loop
    const int e0 = d_off[i], e1 = d_off[i + 1];
    for (int e = e0; e < e1; e++) {
        int s = d_csrc[e];
        float w = d_cnorm[e];
        acc += w * d_hw[(size_t)s * HID + j];
    }
    d_h[(size_t)i * HID + j] = acc + b[j];
}

// ---------------- pooling ----------------
__global__ void __launch_bounds__(128) k_pool(const void* __restrict__ batch) {
    const int i = blockIdx.x;
    const int j = threadIdx.x;
    unsigned g = (unsigned)load_idx(batch, d_is64_batch, i);
    if (g >= NGR) return;
    atomicAdd(&d_pool[g * HID + j], d_h[(size_t)i * HID + j]);
    if (j == 0) atomicAdd(&d_cnt[g], 1.0f);
}

// ---------------- head ----------------
__global__ void k_final(const float* __restrict__ Wlin, const float* __restrict__ blin,
                        float* __restrict__ out) {
    int g = blockIdx.x * blockDim.x + threadIdx.x;
    if (g >= NGR) return;
    float inv = 1.0f / fmaxf(d_cnt[g], 1.0f);
    float a0 = 0.f, a1 = 0.f;
#pragma unroll 8
    for (int j = 0; j < HID; j++) {
        float p = d_pool[g * HID + j] * inv;
        a0 += p * Wlin[j * 2 + 0];
        a1 += p * Wlin[j * 2 + 1];
    }
    out[g * 2 + 0] = a0 + blin[0];
    out[g * 2 + 1] = a1 + blin[1];
}

// ---------------- launch ----------------
extern "C" void kernel_launch(void* const* d_in, const int* in_sizes, int n_in,
                              void* d_out, int out_size) {
    // Resolve inputs by element count — robust to metadata ordering.
    int ix = 0, iei = 1, ibatch = 2, iW1 = 3, iWlin = 11, iblin = 12;
    int iW[3] = {5, 7, 9};
    int ib[4] = {4, 6, 8, 10};
    {
        int nW = 0, nb = 0;
        int fx = -1, fei = -1, fb = -1, fW1 = -1, fWl = -1, fbl = -1;
        int fW[3] = {-1, -1, -1}, fbias[4] = {-1, -1, -1, -1};
        for (int i = 0; i < n_in; i++) {
            switch (in_sizes[i]) {
                case 700000:  fx  = i; break;                       // x: N*7
                case 3200000: fei = i; break;                       // edge_index: 2*E
                case 100000:  fb  = i; break;                       // batch: N
                case 896:     fW1 = i; break;                       // W1: 7*128
                case 16384:   if (nW < 3) fW[nW++] = i; break;      // W2..W4
                case 128:     if (nb < 4) fbias[nb++] = i; break;   // b1..b4
                case 256:     fWl = i; break;                       // Wlin: 128*2
                case 2:       fbl = i; break;                       // blin
                default: break;
            }
        }
        if (fx >= 0 && fei >= 0 && fb >= 0 && fW1 >= 0 && fWl >= 0 && fbl >= 0 &&
            nW == 3 && nb == 4) {
            ix = fx; iei = fei; ibatch = fb; iW1 = fW1; iWlin = fWl; iblin = fbl;
            iW[0] = fW[0]; iW[1] = fW[1]; iW[2] = fW[2];
            ib[0] = fbias[0]; ib[1] = fbias[1]; ib[2] = fbias[2]; ib[3] = fbias[3];
        }
    }

    const float* x     = (const float*)d_in[ix];
    const void*  ei    = d_in[iei];
    const void*  batch = d_in[ibatch];
    const float* W1    = (const float*)d_in[iW1];
    const float* Wlin  = (const float*)d_in[iWlin];
    const float* blin  = (const float*)d_in[iblin];
    float* out = (float*)d_out;

    k_detect<<<1, 1>>>(ei, batch);

    // CSR + normalization (built per call; reused across all 4 layers)
    k_zero<<<512, 256>>>();
    k_hist<<<(NE + 255) / 256, 256>>>(ei);
    k_dinv<<<(NN + 255) / 256, 256>>>();
    k_scan<<<1, 1024>>>();
    k_scatter<<<(NE + 255) / 256, 256>>>(ei);

    // layer 1
    k_gemm7<<<(NN * HID + 255) / 256, 256>>>(x, W1);
    k_agg<<<NN, 128>>>((const float*)d_in[ib[0]]);
    // layers 2..4
    for (int l = 0; l < 3; l++) {
        k_gemm128<<<NN / 32, 256>>>((const float*)d_in[iW[l]]);
        k_agg<<<NN, 128>>>((const float*)d_in[ib[l + 1]]);
    }

    // pool + head
    k_pool<<<NN, 128>>>(batch);
    k_final<<<(NGR + 127) / 128, 128>>>(Wlin, blin, out);
}

// round 4
// speedup vs baseline: 1.6299x; 1.6299x over previous
#include <cuda_runtime.h>

#define NN  100000
#define NNP 100032          // padded to 64-row tiles (pad rows stay zero)
#define NE  1600000
#define NGR 512
#define FIN 7
#define HID 128

// ---------------- scratch (static device globals; zero-initialized) ----------------
__device__ __align__(16) float d_hw[(size_t)NNP * HID];
__device__ __align__(16) float d_h [(size_t)NNP * HID];
__device__ __align__(16) float d_t [(size_t)NN * 2];
__device__ float d_dinv[NN];
__device__ int   d_counts[NN];
__device__ int   d_cursor[NN];
__device__ int   d_off[NN + 1];
__device__ int   d_csrc[NE];
__device__ float d_cnorm[NE];
__device__ float d_pool2[NGR * 2];
__device__ int   d_gcnt[NGR];
__device__ float d_W4p[HID * 2];
__device__ float d_b4p[2];
__device__ int   d_is64_ei;
__device__ int   d_is64_batch;

__device__ __forceinline__ int load_idx(const void* p, int is64, long long i) {
    return is64 ? (int)((const long long*)p)[i] : ((const int*)p)[i];
}

// ---------------- dtype probe (int64 vs int32) ----------------
__global__ void k_detect(const void* ei, const void* batch) {
    const int* w1 = (const int*)ei;
    const int* w2 = (const int*)batch;
    int nz1 = 0, nz2 = 0;
    for (int i = 1; i < 2048; i += 2) { nz1 |= w1[i]; nz2 |= w2[i]; }
    d_is64_ei    = (nz1 == 0);
    d_is64_batch = (nz2 == 0);
}

// ---------------- init ----------------
__global__ void k_zero() {
    int i = blockIdx.x * blockDim.x + threadIdx.x;
    int stride = gridDim.x * blockDim.x;
    for (int t = i; t < NN; t += stride) { d_counts[t] = 0; d_cursor[t] = 0; }
    for (int t = i; t < NGR * 2; t += stride) d_pool2[t] = 0.f;
    for (int t = i; t < NGR; t += stride) d_gcnt[t] = 0;
}

// ---------------- degree histogram (edge destinations) ----------------
__global__ void k_hist(const void* __restrict__ ei) {
    int e = blockIdx.x * blockDim.x + threadIdx.x;
    if (e >= NE) return;
    unsigned d = (unsigned)load_idx(ei, d_is64_ei, (long long)NE + e);
    if (d < NN) atomicAdd(&d_counts[d], 1);
}

// ---------------- nodes-per-graph histogram ----------------
__global__ void k_bhist(const void* __restrict__ batch) {
    int i = blockIdx.x * blockDim.x + threadIdx.x;
    if (i >= NN) return;
    unsigned g = (unsigned)load_idx(batch, d_is64_batch, i);
    if (g < NGR) atomicAdd(&d_gcnt[g], 1);
}

__global__ void k_dinv() {
    int i = blockIdx.x * blockDim.x + threadIdx.x;
    if (i < NN) d_dinv[i] = rsqrtf((float)d_counts[i] + 1.0f);   // +1 self-loop
}

// ---------------- single-block exclusive scan ----------------
__global__ void k_scan() {
    __shared__ int s[1024];
    int t = threadIdx.x;
    const int CH = (NN + 1023) / 1024;
    int lo = t * CH;
    int hi = lo + CH; if (hi > NN) hi = NN; if (lo > NN) lo = NN;
    int sum = 0;
    for (int i = lo; i < hi; i++) sum += d_counts[i];
    s[t] = sum;
    __syncthreads();
    for (int ofs = 1; ofs < 1024; ofs <<= 1) {
        int v = 0;
        if (t >= ofs) v = s[t - ofs];
        __syncthreads();
        if (t >= ofs) s[t] += v;
        __syncthreads();
    }
    int run = (t == 0) ? 0 : s[t - 1];
    for (int i = lo; i < hi; i++) { d_off[i] = run; run += d_counts[i]; }
    if (t == 1023) d_off[NN] = s[1023];
}

// ---------------- scatter edges into CSR (by dst) ----------------
__global__ void k_scatter(const void* __restrict__ ei) {
    int e = blockIdx.x * blockDim.x + threadIdx.x;
    if (e >= NE) return;
    int is64 = d_is64_ei;
    unsigned s = (unsigned)load_idx(ei, is64, e);
    unsigned d = (unsigned)load_idx(ei, is64, (long long)NE + e);
    if (s >= NN || d >= NN) return;
    int pos = d_off[d] + atomicAdd(&d_cursor[d], 1);
    d_csrc[pos] = (int)s;
    d_cnorm[pos] = d_dinv[s] * d_dinv[d];
}

// ---------------- fold: W4p = W4 @ Wlin [128,2]; b4p = b4 @ Wlin + blin ----------------
__global__ void k_fold(const float* __restrict__ W4, const float* __restrict__ b4,
                       const float* __restrict__ Wlin, const float* __restrict__ blin) {
    int j = threadIdx.x;              // 128 threads
    float s0 = 0.f, s1 = 0.f;
#pragma unroll 8
    for (int k = 0; k < HID; k++) {
        float w = W4[j * HID + k];
        s0 += w * Wlin[k * 2 + 0];
        s1 += w * Wlin[k * 2 + 1];
    }
    d_W4p[j * 2 + 0] = s0;
    d_W4p[j * 2 + 1] = s1;
    if (j < 2) {
        float s = 0.f;
        for (int k = 0; k < HID; k++) s += b4[k] * Wlin[k * 2 + j];
        d_b4p[j] = s + blin[j];
    }
}

// ---------------- layer 1 GEMM: x[N,7] @ W1[7,128] -> d_hw ----------------
__global__ void k_gemm7(const float* __restrict__ x, const float* __restrict__ W1) {
    int idx = blockIdx.x * blockDim.x + threadIdx.x;
    if (idx >= NN * HID) return;
    int n = idx >> 7, j = idx & 127;
    float acc = 0.f;
#pragma unroll
    for (int k = 0; k < FIN; k++)
        acc += __ldg(&x[n * FIN + k]) * __ldg(&W1[k * HID + j]);
    d_hw[idx] = acc;
}

// ---------------- 128x128 GEMM: relu(d_h)[64-tile] @ W -> d_hw --------------------
// 256 threads, 64 rows x 128 cols per block, 8x4 outputs/thread, W fully smem-resident.
__global__ void __launch_bounds__(256) k_gemm128(const float* __restrict__ W) {
    extern __shared__ __align__(16) float smem[];
    float* hs = smem;                  // 64*128 = 32 KB
    float* ws = smem + 64 * 128;       // 128*128 = 64 KB
    const int tid = threadIdx.x;
    const int node0 = blockIdx.x * 64;

    // load full W (16384 floats) via float4
    {
        const float4* W4v = (const float4*)W;
        float4* ws4 = (float4*)ws;
#pragma unroll
        for (int i = 0; i < 16; i++) ws4[tid + i * 256] = W4v[tid + i * 256];
    }
    // load 64x128 input tile with relu
    {
        const float4* hin4 = (const float4*)(d_h + (size_t)node0 * HID);
        float4* hs4 = (float4*)hs;
#pragma unroll
        for (int i = 0; i < 8; i++) {
            float4 v = hin4[tid + i * 256];
            v.x = fmaxf(v.x, 0.f); v.y = fmaxf(v.y, 0.f);
            v.z = fmaxf(v.z, 0.f); v.w = fmaxf(v.w, 0.f);
            hs4[tid + i * 256] = v;
        }
    }
    __syncthreads();

    const int tn = tid & 31;           // col group: cols tn*4..+3
    const int tm = tid >> 5;           // row group: rows tm*8..+7
    const int c0 = tn * 4;
    const int r0 = tm * 8;
    float acc[8][4] = {};

#pragma unroll 4
    for (int k = 0; k < 128; k++) {
        float4 bv = *(const float4*)&ws[k * 128 + c0];
#pragma unroll
        for (int u = 0; u < 8; u++) {
            float a = hs[(r0 + u) * 128 + k];
            acc[u][0] += a * bv.x; acc[u][1] += a * bv.y;
            acc[u][2] += a * bv.z; acc[u][3] += a * bv.w;
        }
    }

#pragma unroll
    for (int u = 0; u < 8; u++) {
        float4 o = make_float4(acc[u][0], acc[u][1], acc[u][2], acc[u][3]);
        *(float4*)&d_hw[(size_t)(node0 + r0 + u) * HID + c0] = o;
    }
}

// ---------------- aggregation: d_h = norm-agg(d_hw) + b (warp per node, float4) ----
__global__ void __launch_bounds__(128) k_agg(const float* __restrict__ b) {
    const int lane = threadIdx.x & 31;
    const int i = blockIdx.x * 4 + (threadIdx.x >> 5);
    if (i >= NN) return;
    const float4* hw4 = (const float4*)d_hw;
    const float di = d_dinv[i];
    float4 acc = hw4[(size_t)i * 32 + lane];
    float sw = di * di;
    acc.x *= sw; acc.y *= sw; acc.z *= sw; acc.w *= sw;
    const int e1 = d_off[i + 1];
#pragma unroll 2
    for (int e = d_off[i]; e < e1; e++) {
        int s = d_csrc[e];
        float w = d_cnorm[e];
        float4 v = hw4[(size_t)s * 32 + lane];
        acc.x += w * v.x; acc.y += w * v.y; acc.z += w * v.z; acc.w += w * v.w;
    }
    float4 bv = ((const float4*)b)[lane];
    acc.x += bv.x; acc.y += bv.y; acc.z += bv.z; acc.w += bv.w;
    ((float4*)d_h)[(size_t)i * 32 + lane] = acc;
}

// ---------------- folded layer-4 GEMV: t[N,2] = relu(d_h) @ W4p (warp per node) ----
__global__ void __launch_bounds__(128) k_gemm2() {
    __shared__ float sw[HID * 2];
    const int tid = threadIdx.x;
    sw[tid] = d_W4p[tid];
    sw[tid + 128] = d_W4p[tid + 128];
    __syncthreads();

    const int lane = tid & 31;
    const int i = blockIdx.x * 4 + (tid >> 5);
    if (i >= NN) return;
    float4 a = ((const float4*)d_h)[(size_t)i * 32 + lane];
    a.x = fmaxf(a.x, 0.f); a.y = fmaxf(a.y, 0.f);
    a.z = fmaxf(a.z, 0.f); a.w = fmaxf(a.w, 0.f);
    const int j0 = lane * 4;
    float s0 = a.x * sw[(j0+0)*2]   + a.y * sw[(j0+1)*2]   + a.z * sw[(j0+2)*2]   + a.w * sw[(j0+3)*2];
    float s1 = a.x * sw[(j0+0)*2+1] + a.y * sw[(j0+1)*2+1] + a.z * sw[(j0+2)*2+1] + a.w * sw[(j0+3)*2+1];
#pragma unroll
    for (int o = 16; o > 0; o >>= 1) {
        s0 += __shfl_down_sync(0xffffffffu, s0, o);
        s1 += __shfl_down_sync(0xffffffffu, s1, o);
    }
    if (lane == 0) {
        d_t[i * 2 + 0] = s0;
        d_t[i * 2 + 1] = s1;
    }
}

// ---------------- 2-wide aggregation fused with pooling ----------------
__global__ void k_agg2pool(const void* __restrict__ batch) {
    int i = blockIdx.x * blockDim.x + threadIdx.x;
    if (i >= NN) return;
    const float2* t2 = (const float2*)d_t;
    const float di = d_dinv[i];
    float2 ti = t2[i];
    float sw = di * di;
    float a0 = sw * ti.x, a1 = sw * ti.y;
    const int e1 = d_off[i + 1];
    for (int e = d_off[i]; e < e1; e++) {
        int s = d_csrc[e];
        float w = d_cnorm[e];
        float2 ts = t2[s];
        a0 += w * ts.x; a1 += w * ts.y;
    }
    unsigned g = (unsigned)load_idx(batch, d_is64_batch, i);
    if (g >= NGR) return;
    atomicAdd(&d_pool2[g * 2 + 0], a0);
    atomicAdd(&d_pool2[g * 2 + 1], a1);
}

// ---------------- output: mean + folded bias ----------------
__global__ void k_out(float* __restrict__ out) {
    int idx = blockIdx.x * blockDim.x + threadIdx.x;
    if (idx >= NGR * 2) return;
    int g = idx >> 1, c = idx & 1;
    float cnt = fmaxf((float)d_gcnt[g], 1.0f);
    out[idx] = d_pool2[g * 2 + c] / cnt + d_b4p[c];
}

// ---------------- launch ----------------
extern "C" void kernel_launch(void* const* d_in, const int* in_sizes, int n_in,
                              void* d_out, int out_size) {
    // Resolve inputs by element count — robust to metadata ordering.
    int ix = 0, iei = 1, ibatch = 2, iW1 = 3, iWlin = 11, iblin = 12;
    int iW[3] = {5, 7, 9};
    int ib[4] = {4, 6, 8, 10};
    {
        int nW = 0, nb = 0;
        int fx = -1, fei = -1, fb = -1, fW1 = -1, fWl = -1, fbl = -1;
        int fW[3] = {-1, -1, -1}, fbias[4] = {-1, -1, -1, -1};
        for (int i = 0; i < n_in; i++) {
            switch (in_sizes[i]) {
                case 700000:  fx  = i; break;
                case 3200000: fei = i; break;
                case 100000:  fb  = i; break;
                case 896:     fW1 = i; break;
                case 16384:   if (nW < 3) fW[nW++] = i; break;
                case 128:     if (nb < 4) fbias[nb++] = i; break;
                case 256:     fWl = i; break;
                case 2:       fbl = i; break;
                default: break;
            }
        }
        if (fx >= 0 && fei >= 0 && fb >= 0 && fW1 >= 0 && fWl >= 0 && fbl >= 0 &&
            nW == 3 && nb == 4) {
            ix = fx; iei = fei; ibatch = fb; iW1 = fW1; iWlin = fWl; iblin = fbl;
            iW[0] = fW[0]; iW[1] = fW[1]; iW[2] = fW[2];
            ib[0] = fbias[0]; ib[1] = fbias[1]; ib[2] = fbias[2]; ib[3] = fbias[3];
        }
    }

    const float* x     = (const float*)d_in[ix];
    const void*  ei    = d_in[iei];
    const void*  batch = d_in[ibatch];
    const float* W1    = (const float*)d_in[iW1];
    float* out = (float*)d_out;

    static int smem_set = 0;
    cudaFuncSetAttribute(k_gemm128, cudaFuncAttributeMaxDynamicSharedMemorySize, 96 * 1024);
    (void)smem_set;

    k_detect<<<1, 1>>>(ei, batch);
    k_zero<<<512, 256>>>();
    k_hist<<<(NE + 255) / 256, 256>>>(ei);
    k_bhist<<<(NN + 255) / 256, 256>>>(batch);
    k_dinv<<<(NN + 255) / 256, 256>>>();
    k_scan<<<1, 1024>>>();
    k_scatter<<<(NE + 255) / 256, 256>>>(ei);
    k_fold<<<1, 128>>>((const float*)d_in[iW[2]], (const float*)d_in[ib[3]],
                       (const float*)d_in[iWlin], (const float*)d_in[iblin]);

    // layer 1
    k_gemm7<<<(NN * HID + 255) / 256, 256>>>(x, W1);
    k_agg<<<NN / 4, 128>>>((const float*)d_in[ib[0]]);
    // layers 2, 3 (full 128x128)
    k_gemm128<<<NNP / 64, 256, 96 * 1024>>>((const float*)d_in[iW[0]]);
    k_agg<<<NN / 4, 128>>>((const float*)d_in[ib[1]]);
    k_gemm128<<<NNP / 64, 256, 96 * 1024>>>((const float*)d_in[iW[1]]);
    k_agg<<<NN / 4, 128>>>((const float*)d_in[ib[2]]);
    // folded layer 4 + pool + head
    k_gemm2<<<NN / 4, 128>>>();
    k_agg2pool<<<(NN + 255) / 256, 256>>>(batch);
    k_out<<<(NGR * 2 + 255) / 256, 256>>>(out);
}